// round 1
// baseline (speedup 1.0000x reference)
#include <cuda_runtime.h>
#include <cuda_bf16.h>

// HierarchicalSoftmaxLoss: depth-2 tree, B=128, BATCH=4096, PRED_SIZE=16512.
// loss(row) = LSE(pred[0:128]) - pred[p]
//           + LSE(pred[128 + p*128 : 128 + (p+1)*128]) - pred[128 + p*128 + c]
// where p = target>>7, c = target&127. Output = mean over batch.
//
// Only 256 floats per row are needed -> ~4.2 MB total traffic.
// One warp per row; float4 vectorized loads; shfl reductions; one atomicAdd
// per CTA into the scalar output.

#define HSM_B        128
#define HSM_BATCH    4096
#define HSM_PRED     16512
#define WARPS_PER_CTA 8

__global__ void hsm_zero_kernel(float* out) { out[0] = 0.0f; }

__device__ __forceinline__ float warp_lse_and_pick(float4 v, int idx, float& picked) {
    // 32 lanes hold 128 floats (lane l holds elements 4l..4l+3).
    // Returns logsumexp over the 128 values; picked = element [idx] (idx uniform per warp).
    float m = fmaxf(fmaxf(v.x, v.y), fmaxf(v.z, v.w));
    #pragma unroll
    for (int o = 16; o; o >>= 1) m = fmaxf(m, __shfl_xor_sync(0xFFFFFFFFu, m, o));
    float s = __expf(v.x - m) + __expf(v.y - m) + __expf(v.z - m) + __expf(v.w - m);
    #pragma unroll
    for (int o = 16; o; o >>= 1) s += __shfl_xor_sync(0xFFFFFFFFu, s, o);
    // idx is warp-uniform: select the sub-element locally, then broadcast from owning lane.
    const float* e = reinterpret_cast<const float*>(&v);
    float local = e[idx & 3];
    picked = __shfl_sync(0xFFFFFFFFu, local, idx >> 2);
    return __logf(s) + m;
}

__global__ __launch_bounds__(WARPS_PER_CTA * 32, 1)
void hsm_loss_kernel(const float* __restrict__ pred,
                     const int*   __restrict__ targets,
                     float*       __restrict__ out) {
    __shared__ float warp_loss[WARPS_PER_CTA];

    const int warp = threadIdx.x >> 5;
    const int lane = threadIdx.x & 31;
    const int row  = blockIdx.x * WARPS_PER_CTA + warp;

    const float* rowp = pred + (size_t)row * HSM_PRED;
    const int t = targets[row];
    const int p = t >> 7;      // parent index (level-1 class)
    const int c = t & 127;     // child index within parent's segment

    // Level 1: root segment pred[0:128]
    float4 v1 = reinterpret_cast<const float4*>(rowp)[lane];
    // Level 2: child segment pred[128 + p*128 : +128]  (16B-aligned: offset mult of 128 floats)
    float4 v2 = reinterpret_cast<const float4*>(rowp + HSM_B + p * HSM_B)[lane];

    float tgt1, tgt2;
    float lse1 = warp_lse_and_pick(v1, p, tgt1);
    float lse2 = warp_lse_and_pick(v2, c, tgt2);

    float loss = (lse1 - tgt1) + (lse2 - tgt2);

    if (lane == 0) warp_loss[warp] = loss;
    __syncthreads();

    if (warp == 0) {
        float s = (lane < WARPS_PER_CTA) ? warp_loss[lane] : 0.0f;
        #pragma unroll
        for (int o = 4; o; o >>= 1) s += __shfl_xor_sync(0xFFFFFFFFu, s, o);
        if (lane == 0) atomicAdd(out, s * (1.0f / HSM_BATCH));
    }
}

extern "C" void kernel_launch(void* const* d_in, const int* in_sizes, int n_in,
                              void* d_out, int out_size) {
    const float* pred    = (const float*)d_in[0];
    const int*   targets = (const int*)d_in[1];
    float*       out     = (float*)d_out;

    hsm_zero_kernel<<<1, 1>>>(out);
    hsm_loss_kernel<<<HSM_BATCH / WARPS_PER_CTA, WARPS_PER_CTA * 32>>>(pred, targets, out);
}